// round 17
// baseline (speedup 1.0000x reference)
#include <cuda_runtime.h>
#include <cuda_bf16.h>
#include <cstdint>

#define N_NODES 200000
#define N_EDGES 6400000
#define N_LAYERS 3

// Scratch (no cudaMalloc allowed)
__device__ float4 g_T[N_NODES];    // (t0, t1, t2, deg) accumulators
__device__ float  g_A1[N_NODES];   // layer-1 per-node scalar
__device__ float2 g_P[N_NODES];    // (c, q1): c node-local, q1 RED'd by pass 1
__device__ float  g_q2[N_NODES];   // M @ A_2

// PDL primitive: wait for stream predecessor (implicit trigger at completion)
__device__ __forceinline__ void pdl_wait() {
    asm volatile("griddepcontrol.wait;" ::: "memory");
}

// ---------------------------------------------------------------------------
__device__ __forceinline__ void red_add_v4(float4* ptr, float a, float b,
                                           float c, float d) {
    asm volatile("red.global.add.v4.f32 [%0], {%1, %2, %3, %4};"
                 :: "l"(__cvta_generic_to_global(ptr)),
                    "f"(a), "f"(b), "f"(c), "f"(d)
                 : "memory");
}

// ---------------------------------------------------------------------------
// 1. ONE heavy edge pass for all 3 layers, 4 edges per thread:
//    T[dst] += ( ws_l.z0[src] + w_geo_l.(r,rhat)  for l=0..2 , 1 )
//    Weights loaded directly from W (uniform broadcast loads, L1-resident).
// ---------------------------------------------------------------------------
__global__ void __launch_bounds__(256)
heavy_edge_kernel(const int4* __restrict__ src4,
                  const int4* __restrict__ dst4,
                  const float4* __restrict__ r4,
                  const float4* __restrict__ rhat4,
                  const float4* __restrict__ z0,
                  const float* __restrict__ W,
                  float4* __restrict__ T) {
    pdl_wait();
    int t = blockIdx.x * blockDim.x + threadIdx.x;   // grid exact: no OOB

    int4   s  = __ldcs(src4 + t);
    int4   d  = __ldcs(dst4 + t);
    float4 r  = __ldcs(r4   + t);
    float4 h0 = __ldcs(rhat4 + 3 * t + 0);
    float4 h1 = __ldcs(rhat4 + 3 * t + 1);
    float4 h2 = __ldcs(rhat4 + 3 * t + 2);

    float4 zs0 = __ldg(&z0[s.x]);
    float4 zs1 = __ldg(&z0[s.y]);
    float4 zs2 = __ldg(&z0[s.z]);
    float4 zs3 = __ldg(&z0[s.w]);

    float rr[4]    = {r.x, r.y, r.z, r.w};
    float rh[4][3] = {{h0.x, h0.y, h0.z}, {h0.w, h1.x, h1.y},
                      {h1.z, h1.w, h2.x}, {h2.y, h2.z, h2.w}};
    float4 zs[4]   = {zs0, zs1, zs2, zs3};
    int    dd[4]   = {d.x, d.y, d.z, d.w};

    float tv[4][3];
    #pragma unroll
    for (int l = 0; l < N_LAYERS; l++) {
        const float* wr = W + l * 12;
        float w0 = __ldg(wr + 0), w1 = __ldg(wr + 1);
        float w2 = __ldg(wr + 2), w3 = __ldg(wr + 3);
        float w8 = __ldg(wr + 8), w9 = __ldg(wr + 9);
        float wa = __ldg(wr + 10), wb = __ldg(wr + 11);
        #pragma unroll
        for (int e = 0; e < 4; e++) {
            tv[e][l] = w0 * zs[e].x + w1 * zs[e].y + w2 * zs[e].z + w3 * zs[e].w
                     + w8 * rr[e] + w9 * rh[e][0] + wa * rh[e][1] + wb * rh[e][2];
        }
    }

    #pragma unroll
    for (int e = 0; e < 4; e++)
        red_add_v4(&T[dd[e]], tv[e][0], tv[e][1], tv[e][2], 1.f);
}

// ---------------------------------------------------------------------------
// 2. Node layer 0/1 prep:
//    A1 = t0 + deg*(b0 + wd0.z0)
//    c  = A1 + t1 + deg*(b1 + wd1.z0 + sB1*A1)
//    P  = (c, 0);  out_x = z0
// ---------------------------------------------------------------------------
__global__ void node0_kernel(const float4* __restrict__ z0,
                             const float4* __restrict__ T,
                             const float* __restrict__ W,
                             const float* __restrict__ b,
                             float* __restrict__ A1,
                             float2* __restrict__ P,
                             float4* __restrict__ out) {
    pdl_wait();
    int n = blockIdx.x * blockDim.x + threadIdx.x;
    if (n >= N_NODES) return;
    // layer 0 dst weights
    float d00 = __ldg(W + 4),  d01 = __ldg(W + 5);
    float d02 = __ldg(W + 6),  d03 = __ldg(W + 7);
    float b0  = __ldg(b + 0);
    // layer 1 dst weights
    float d10 = __ldg(W + 16), d11 = __ldg(W + 17);
    float d12 = __ldg(W + 18), d13 = __ldg(W + 19);
    float b1  = __ldg(b + 1);
    float sB1 = d10 + d11 + d12 + d13;

    float4 z = z0[n];
    float4 tt = T[n];
    float pd0 = b0 + d00*z.x + d01*z.y + d02*z.z + d03*z.w;
    float a1 = tt.x + tt.w * pd0;
    float pd1 = b1 + d10*z.x + d11*z.y + d12*z.z + d13*z.w + sB1 * a1;
    float c = a1 + tt.y + tt.w * pd1;
    A1[n] = a1;
    P[n] = make_float2(c, 0.f);
    out[N_NODES + n] = z;           // x output
}

// ---------------------------------------------------------------------------
// 3. Light pass 1: P[dst].y += A1[src]   (q1 accumulation)
// ---------------------------------------------------------------------------
__global__ void __launch_bounds__(256)
light1_kernel(const int4* __restrict__ src4,
              const int4* __restrict__ dst4,
              const float* __restrict__ A1,
              float2* __restrict__ P) {
    pdl_wait();
    int t = blockIdx.x * blockDim.x + threadIdx.x;   // grid exact: no OOB

    int4 s = __ldcs(src4 + t);
    int4 d = __ldcs(dst4 + t);

    float a0 = __ldg(&A1[s.x]);
    float a1 = __ldg(&A1[s.y]);
    float a2 = __ldg(&A1[s.z]);
    float a3 = __ldg(&A1[s.w]);

    atomicAdd(&P[d.x].y, a0);
    atomicAdd(&P[d.y].y, a1);
    atomicAdd(&P[d.z].y, a2);
    atomicAdd(&P[d.w].y, a3);
}

// ---------------------------------------------------------------------------
// 4. Light pass 2: q2[dst] += c[src] + sA1*q1[src]   (= A2[src], on the fly)
// ---------------------------------------------------------------------------
__global__ void __launch_bounds__(256)
light2_kernel(const int4* __restrict__ src4,
              const int4* __restrict__ dst4,
              const float2* __restrict__ P,
              const float* __restrict__ W,
              float* __restrict__ q2) {
    pdl_wait();
    int t = blockIdx.x * blockDim.x + threadIdx.x;   // grid exact: no OOB

    int4 s = __ldcs(src4 + t);
    int4 d = __ldcs(dst4 + t);
    // sA1 = sum of layer-1 src weights
    float sA1 = __ldg(W + 12) + __ldg(W + 13) + __ldg(W + 14) + __ldg(W + 15);

    float2 p0 = __ldg(&P[s.x]);
    float2 p1 = __ldg(&P[s.y]);
    float2 p2 = __ldg(&P[s.z]);
    float2 p3 = __ldg(&P[s.w]);

    atomicAdd(&q2[d.x], fmaf(sA1, p0.y, p0.x));
    atomicAdd(&q2[d.y], fmaf(sA1, p1.y, p1.x));
    atomicAdd(&q2[d.z], fmaf(sA1, p2.y, p2.x));
    atomicAdd(&q2[d.w], fmaf(sA1, p3.y, p3.x));
}

// ---------------------------------------------------------------------------
// 5. Final: A2 = c + sA1*q1;
//    A3 = A2 + t2 + sA2*q2 + deg*(b2 + wd2.z0 + sB2*A2);  out_z = z0 + A3
// ---------------------------------------------------------------------------
__global__ void final_kernel(const float4* __restrict__ z0,
                             const float4* __restrict__ T,
                             const float2* __restrict__ P,
                             const float* __restrict__ q2,
                             const float* __restrict__ W,
                             const float* __restrict__ b,
                             float4* __restrict__ out) {
    pdl_wait();
    int n = blockIdx.x * blockDim.x + threadIdx.x;
    if (n >= N_NODES) return;
    float sA1 = __ldg(W + 12) + __ldg(W + 13) + __ldg(W + 14) + __ldg(W + 15);
    float s20 = __ldg(W + 24), s21 = __ldg(W + 25);
    float s22 = __ldg(W + 26), s23 = __ldg(W + 27);
    float sA2 = s20 + s21 + s22 + s23;
    float d20 = __ldg(W + 28), d21 = __ldg(W + 29);
    float d22 = __ldg(W + 30), d23 = __ldg(W + 31);
    float sB2 = d20 + d21 + d22 + d23;
    float b2  = __ldg(b + 2);

    float4 z = z0[n];
    float4 tt = T[n];
    float2 p = P[n];
    float a2 = fmaf(sA1, p.y, p.x);
    float pd = b2 + d20*z.x + d21*z.y + d22*z.z + d23*z.w + sB2 * a2;
    float a3 = a2 + tt.z + sA2 * q2[n] + tt.w * pd;
    out[n] = make_float4(z.x + a3, z.y + a3, z.z + a3, z.w + a3);
}

// ---------------------------------------------------------------------------
// PDL launch helper (serialization only — proven config)
// ---------------------------------------------------------------------------
template <typename... Args>
static void launch_pdl(void (*kern)(Args...), dim3 grid, dim3 block,
                       Args... args) {
    cudaLaunchAttribute attr[1];
    attr[0].id = cudaLaunchAttributeProgrammaticStreamSerialization;
    attr[0].val.programmaticStreamSerializationAllowed = 1;
    cudaLaunchConfig_t cfg = {};
    cfg.gridDim = grid;
    cfg.blockDim = block;
    cfg.dynamicSmemBytes = 0;
    cfg.stream = 0;
    cfg.attrs = attr;
    cfg.numAttrs = 1;
    cudaLaunchKernelEx(&cfg, kern, args...);
}

// ---------------------------------------------------------------------------
extern "C" void kernel_launch(void* const* d_in, const int* in_sizes, int n_in,
                              void* d_out, int out_size) {
    const float* z    = (const float*)d_in[0];
    const float* r    = (const float*)d_in[1];
    const float* rhat = (const float*)d_in[2];
    const float* W    = (const float*)d_in[3];
    const float* b    = (const float*)d_in[4];
    const int*   src  = (const int*)d_in[5];
    const int*   dst  = (const int*)d_in[6];
    float* out = (float*)d_out;

    float4 *T; float *A1, *q2; float2 *P;
    cudaGetSymbolAddress((void**)&T,  g_T);
    cudaGetSymbolAddress((void**)&A1, g_A1);
    cudaGetSymbolAddress((void**)&P,  g_P);
    cudaGetSymbolAddress((void**)&q2, g_q2);

    const dim3 blk(256);
    const dim3 NODE_GRID((N_NODES + 255) / 256);
    const dim3 EDGE_GRID(N_EDGES / 4 / 256);   // exact: 6250

    // Zero the RED accumulators via memset nodes (cheaper than an init kernel;
    // stream order guarantees completion before the heavy pass's REDs).
    cudaMemsetAsync(T,  0, N_NODES * sizeof(float4), 0);
    cudaMemsetAsync(q2, 0, N_NODES * sizeof(float),  0);

    launch_pdl(heavy_edge_kernel, EDGE_GRID, blk,
               (const int4*)src, (const int4*)dst,
               (const float4*)r, (const float4*)rhat,
               (const float4*)z, W, T);

    launch_pdl(node0_kernel, NODE_GRID, blk,
               (const float4*)z, (const float4*)T, W, b, A1, P, (float4*)out);

    launch_pdl(light1_kernel, EDGE_GRID, blk,
               (const int4*)src, (const int4*)dst, (const float*)A1, P);

    launch_pdl(light2_kernel, EDGE_GRID, blk,
               (const int4*)src, (const int4*)dst, (const float2*)P, W, q2);

    launch_pdl(final_kernel, NODE_GRID, blk,
               (const float4*)z, (const float4*)T, (const float2*)P,
               (const float*)q2, W, b, (float4*)out);
}